// round 17
// baseline (speedup 1.0000x reference)
#include <cuda_runtime.h>

// LJ_8718783611256: log_prob = -(LJ pair potential + harmonic confinement)
// x: (4, 2048, 3) float32, out: (4,) float32
//
// R12: consolidation. The measured champion kernel (R3: TPB=128, one i-row
// per thread, full 128x128 triangle tiles, warp-broadcast float4 smem loads,
// 9.0us) combined with the champion packaging (single launch, device-global
// accumulators + last-block finalize, ~0.5us e2e overhead vs ~3us with a
// memset node). Nothing else changed — every deviation from this shape
// (NI>4 breaking LDS broadcast, reg caps spilling, 2-wave grids, packed PTX)
// measured neutral or worse.

#define NB      4
#define NPTS    2048
#define IT      128          // i-rows per tile == TPB
#define JT      128          // j-cols per tile
#define TPB     128
#define NCHUNK  (NPTS / JT)  // 16
#define NTRI    (NCHUNK * (NCHUNK + 1) / 2)  // 136
#define NBLK    (NTRI + 1)                   // blocks per batch = 137

__device__ float g_acc[NB];          // zero-initialized at module load
__device__ unsigned int g_cnt[NB];   // zero-initialized at module load

#define RCP(d, s) \
    asm("rcp.approx.f32 %0, %1;" : "=f"(d) : "f"(s))

template <bool DIAG>
__device__ __forceinline__ float lj_row(const float4* __restrict__ sj,
                                        float xi, float yi, float zi) {
    float a12 = 0.f, a6 = 0.f;
    #pragma unroll 8
    for (int jj = 0; jj < JT; jj++) {
        const float4 p = sj[jj];          // warp-broadcast LDS.128
        float dx = xi - p.x;
        float dy = yi - p.y;
        float dz = zi - p.z;
        float sq = dx * dx;
        sq = fmaf(dy, dy, sq);
        sq = fmaf(dz, dz, sq);
        if (DIAG) {
            // i == j gives sq == 0 exactly; push to huge -> rcp -> ~0
            sq = (sq == 0.f) ? 3e38f : sq;
        }
        float inv;
        RCP(inv, sq);
        float i3 = inv * inv * inv;       // d^-6
        a12 = fmaf(i3, i3, a12);          // sum d^-12
        a6 += i3;                         // sum d^-6
    }
    return a12 - a6;
}

__global__ __launch_bounds__(TPB) void lj_tri_kernel(const float* __restrict__ x,
                                                     float* __restrict__ out) {
    const int b = blockIdx.z;
    const float* xb = x + b * NPTS * 3;
    const int t = threadIdx.x;
    const int w = t >> 5, lane = t & 31;

    float contrib = 0.f;   // this block's contribution (thread 0 only)

    if (blockIdx.x == NBLK - 1) {
        // ---------------- harmonic block ----------------
        float sx = 0.f, sy = 0.f, sz = 0.f, s2 = 0.f;
        for (int i = t; i < NPTS; i += TPB) {
            float px = xb[3 * i + 0];
            float py = xb[3 * i + 1];
            float pz = xb[3 * i + 2];
            sx += px; sy += py; sz += pz;
            s2 = fmaf(px, px, s2);
            s2 = fmaf(py, py, s2);
            s2 = fmaf(pz, pz, s2);
        }
        #pragma unroll
        for (int o = 16; o; o >>= 1) {
            sx += __shfl_xor_sync(0xffffffffu, sx, o);
            sy += __shfl_xor_sync(0xffffffffu, sy, o);
            sz += __shfl_xor_sync(0xffffffffu, sz, o);
            s2 += __shfl_xor_sync(0xffffffffu, s2, o);
        }
        __shared__ float red[4][TPB / 32];
        if (lane == 0) { red[0][w] = sx; red[1][w] = sy; red[2][w] = sz; red[3][w] = s2; }
        __syncthreads();
        if (t == 0) {
            float tx = 0.f, ty = 0.f, tz = 0.f, t2 = 0.f;
            #pragma unroll
            for (int k = 0; k < TPB / 32; k++) {
                tx += red[0][k]; ty += red[1][k]; tz += red[2][k]; t2 += red[3][k];
            }
            float com2 = (tx * tx + ty * ty + tz * tz) * (1.0f / NPTS);
            contrib = -0.25f * (t2 - com2);  // -(0.5 * k(=0.5) * sum((x-com)^2))
        }
    } else {
        // ---------------- triangle tile mapping (integer, one-time) ----------
        const int tid = blockIdx.x;
        int by = 0;
        {
            int rem = tid;
            while (rem >= by + 1) { rem -= by + 1; by++; }
        }
        const int bx = tid - by * (by + 1) / 2;
        const bool diag = (bx == by);

        // ---------------- stage j tile as float4 ----------------
        __shared__ float4 sj[JT];
        const int j0 = bx * JT;
        {
            const float* p = xb + (j0 + t) * 3;
            sj[t] = make_float4(p[0], p[1], p[2], 0.f);
        }
        __syncthreads();

        // one i-row per thread; all lanes of a warp sweep the same j sequence
        const int i = by * IT + t;
        const float xi = xb[3 * i + 0];
        const float yi = xb[3 * i + 1];
        const float zi = xb[3 * i + 2];

        float pot = diag ? lj_row<true>(sj, xi, yi, zi)
                         : lj_row<false>(sj, xi, yi, zi);

        #pragma unroll
        for (int o = 16; o; o >>= 1)
            pot += __shfl_xor_sync(0xffffffffu, pot, o);

        __shared__ float wsum[TPB / 32];
        if (lane == 0) wsum[w] = pot;
        __syncthreads();

        if (t == 0) {
            float v = 0.f;
            #pragma unroll
            for (int k = 0; k < TPB / 32; k++) v += wsum[k];
            // epsilon*4 factor folded here; off-diag tiles count each unordered
            // pair once (weight 4.0), diag tiles are full ordered (weight 2.0).
            // Negated for log_prob.
            contrib = diag ? (-2.0f * v) : (-4.0f * v);
        }
    }

    // ---------------- accumulate + last-block finalize ----------------
    if (t == 0) {
        atomicAdd(&g_acc[b], contrib);
        __threadfence();
        unsigned int done = atomicAdd(&g_cnt[b], 1u);
        if (done == NBLK - 1) {
            out[b] = g_acc[b];
            g_acc[b] = 0.f;      // reset for next graph replay
            g_cnt[b] = 0u;
        }
    }
}

extern "C" void kernel_launch(void* const* d_in, const int* in_sizes, int n_in,
                              void* d_out, int out_size) {
    const float* x = (const float*)d_in[0];
    float* out = (float*)d_out;

    dim3 grid(NBLK, 1, NB);  // 136 full tiles + 1 harmonic, x4 batches = 548
    lj_tri_kernel<<<grid, TPB>>>(x, out);
}